// round 3
// baseline (speedup 1.0000x reference)
#include <cuda_runtime.h>
#include <cuda_bf16.h>
#include <math.h>
#include <stdint.h>

typedef __nv_bfloat16 bf16;

#define B_   2
#define L_   1024
#define DM   2048
#define DI   4096
#define DS   16
#define DTR  128
#define T_   (B_*L_)        // 2048 tokens
#define NX   160            // dt_rank + 2*d_state
#define NXPAD 256
#define KSPLITS 8
#define ASTR 40             // smem row stride (bf16 elems), conflict-free for frag loads

// ---------------- scratch (static __device__ arrays; no allocation) ----------------
__device__ float g_xz   [(size_t)T_*2*DI];          // in_proj output (fp32)
__device__ float g_xc   [(size_t)T_*DI];            // conv+silu(x) fp32 (scan input)
__device__ float g_xdblp[(size_t)KSPLITS*T_*NXPAD]; // split-K partials
__device__ float g_xdbl [(size_t)T_*NX];
__device__ float g_dt   [(size_t)T_*DI];
__device__ float g_ys   [(size_t)T_*DI];

// split-bf16 activation / weight buffers
__device__ bf16 g_hsh[(size_t)T_*DM],   g_hsl[(size_t)T_*DM];
__device__ bf16 g_xch[(size_t)T_*DI],   g_xcl[(size_t)T_*DI];
__device__ bf16 g_xdh[(size_t)T_*NX],   g_xdl[(size_t)T_*NX];
__device__ bf16 g_yh [(size_t)T_*DI],   g_yl [(size_t)T_*DI];
__device__ bf16 g_wip_h[(size_t)2*DI*DM], g_wip_l[(size_t)2*DI*DM];
__device__ bf16 g_wxp_h[(size_t)NXPAD*DI], g_wxp_l[(size_t)NXPAD*DI];
__device__ bf16 g_wdt_h[(size_t)DI*DTR],  g_wdt_l[(size_t)DI*DTR];
__device__ bf16 g_wop_h[(size_t)DM*DI],   g_wop_l[(size_t)DM*DI];

// ---------------- helpers ----------------
__device__ __forceinline__ float siluf(float x) { return x / (1.0f + expf(-x)); }
__device__ __forceinline__ float softplusf(float x) { return (x > 20.0f) ? x : log1pf(expf(x)); }
__device__ __forceinline__ void split2(float x, bf16& h, bf16& l) {
    h = __float2bfloat16(x);
    l = __float2bfloat16(x - __bfloat162float(h));
}

// ---------------- weight splitters ----------------
__global__ void wsplit4(const float* __restrict__ w, bf16* __restrict__ hi,
                        bf16* __restrict__ lo, int n4) {
    int i = blockIdx.x * 256 + threadIdx.x;
    if (i >= n4) return;
    float4 v = ((const float4*)w)[i];
    bf16 h0, h1, h2, h3, l0, l1, l2, l3;
    split2(v.x, h0, l0); split2(v.y, h1, l1);
    split2(v.z, h2, l2); split2(v.w, h3, l3);
    ((__nv_bfloat162*)hi)[2 * i + 0] = __nv_bfloat162(h0, h1);
    ((__nv_bfloat162*)hi)[2 * i + 1] = __nv_bfloat162(h2, h3);
    ((__nv_bfloat162*)lo)[2 * i + 0] = __nv_bfloat162(l0, l1);
    ((__nv_bfloat162*)lo)[2 * i + 1] = __nv_bfloat162(l2, l3);
}

// x_proj weights padded from [160][4096] to [256][4096] (zero rows 160..255)
__global__ void wsplit_pad(const float* __restrict__ w, bf16* __restrict__ hi,
                           bf16* __restrict__ lo) {
    int idx = blockIdx.x * 256 + threadIdx.x;   // over NXPAD*DI
    int n = idx >> 12;          // /4096
    int k = idx & (DI - 1);
    float v = (n < NX) ? w[(size_t)n * DI + k] : 0.f;
    bf16 h, l; split2(v, h, l);
    hi[idx] = h; lo[idx] = l;
}

// ---------------- 1) fused add + RMSNorm -> split bf16 hs ----------------
__global__ void addnorm_kernel(const float* __restrict__ h, const float* __restrict__ r,
                               const float* __restrict__ w, float* __restrict__ resid_out,
                               bf16* __restrict__ hsh, bf16* __restrict__ hsl) {
    int t = blockIdx.x;
    int tid = threadIdx.x;
    const float* hp = h + (size_t)t * DM;
    const float* rp = r + (size_t)t * DM;
    float v[8];
    float ss = 0.f;
#pragma unroll
    for (int i = 0; i < 8; i++) {
        int c = tid + i * 256;
        float x = hp[c] + rp[c];
        v[i] = x;
        ss += x * x;
    }
    __shared__ float red[256];
    red[tid] = ss;
    __syncthreads();
    for (int s = 128; s > 0; s >>= 1) {
        if (tid < s) red[tid] += red[tid + s];
        __syncthreads();
    }
    float scale = rsqrtf(red[0] / (float)DM + 1e-5f);
#pragma unroll
    for (int i = 0; i < 8; i++) {
        int c = tid + i * 256;
        if (resid_out) resid_out[(size_t)t * DM + c] = v[i];
        float y = v[i] * scale * w[c];
        bf16 hh, ll; split2(y, hh, ll);
        hsh[(size_t)t * DM + c] = hh;
        hsl[(size_t)t * DM + c] = ll;
    }
}

// ---------------- 2) split-bf16 tensor-core GEMM ----------------
// C[M,N] = A[M,K] * W[N,K]^T with A = Ahi+Alo, W = Whi+Wlo (drop lo*lo).
// 128x128 CTA tile, 8 warps (2x4), warp tile 64x32, BK=32, cp.async double buffer.
// blockIdx.z = split-K slab (writes C + z*M*ldc), klen = K handled per slab.
// EPI==1: softplus(v + bias[n]).
template<int EPI>
__global__ void __launch_bounds__(256, 2)
bgemm(const bf16* __restrict__ Ahi, const bf16* __restrict__ Alo,
      const bf16* __restrict__ Whi, const bf16* __restrict__ Wlo,
      float* __restrict__ C, int M, int N, int lda, int ldw, int ldc,
      int klen, const float* __restrict__ bias) {
    __shared__ __align__(16) bf16 As[2][128][ASTR];
    __shared__ __align__(16) bf16 Wsm[2][128][ASTR];
    int tid = threadIdx.x;
    int m0 = blockIdx.y * 128, n0 = blockIdx.x * 128;
    int kstart = blockIdx.z * klen;
    int KS = klen / 32;
    int S = 3 * KS;
    float* Cb = C + (size_t)blockIdx.z * M * ldc;

    int r = tid >> 1;
    int cc = (tid & 1) * 16;
    uint32_t sa_base[2], sw_base[2];
#pragma unroll
    for (int b = 0; b < 2; b++) {
        sa_base[b] = (uint32_t)__cvta_generic_to_shared(&As[b][r][cc]);
        sw_base[b] = (uint32_t)__cvta_generic_to_shared(&Wsm[b][r][cc]);
    }

    int warp = tid >> 5, lane = tid & 31;
    int wm = (warp >> 2) * 64;
    int wn = (warp & 3) * 32;
    int lr = lane >> 2;
    int lc = (lane & 3) * 2;

    float acc[4][4][4];
#pragma unroll
    for (int mt = 0; mt < 4; mt++)
#pragma unroll
        for (int nt = 0; nt < 4; nt++)
#pragma unroll
            for (int q = 0; q < 4; q++) acc[mt][nt][q] = 0.f;

    auto issue = [&](int s, int buf) {
        int p = s / KS;
        int kk = kstart + (s - p * KS) * 32;
        const bf16* Ag = (p == 1 ? Alo : Ahi) + (size_t)(m0 + r) * lda + kk + cc;
        const bf16* Wg = (p == 2 ? Wlo : Whi) + (size_t)(n0 + r) * ldw + kk + cc;
        asm volatile("cp.async.cg.shared.global [%0], [%1], 16;\n" ::"r"(sa_base[buf]), "l"(Ag));
        asm volatile("cp.async.cg.shared.global [%0], [%1], 16;\n" ::"r"(sa_base[buf] + 16), "l"(Ag + 8));
        asm volatile("cp.async.cg.shared.global [%0], [%1], 16;\n" ::"r"(sw_base[buf]), "l"(Wg));
        asm volatile("cp.async.cg.shared.global [%0], [%1], 16;\n" ::"r"(sw_base[buf] + 16), "l"(Wg + 8));
        asm volatile("cp.async.commit_group;\n");
    };

    issue(0, 0);
    for (int s = 0; s < S; s++) {
        int buf = s & 1;
        if (s + 1 < S) {
            issue(s + 1, buf ^ 1);
            asm volatile("cp.async.wait_group 1;\n");
        } else {
            asm volatile("cp.async.wait_group 0;\n");
        }
        __syncthreads();
#pragma unroll
        for (int ko = 0; ko < 32; ko += 16) {
            uint32_t bfr[4][2];
#pragma unroll
            for (int nt = 0; nt < 4; nt++) {
                const bf16* wp = &Wsm[buf][wn + nt * 8 + lr][ko + lc];
                bfr[nt][0] = *(const uint32_t*)wp;
                bfr[nt][1] = *(const uint32_t*)(wp + 8);
            }
#pragma unroll
            for (int mt = 0; mt < 4; mt++) {
                const bf16* ap = &As[buf][wm + mt * 16 + lr][ko + lc];
                uint32_t a0 = *(const uint32_t*)ap;
                uint32_t a1 = *(const uint32_t*)(ap + 8 * ASTR);
                uint32_t a2 = *(const uint32_t*)(ap + 8);
                uint32_t a3 = *(const uint32_t*)(ap + 8 * ASTR + 8);
#pragma unroll
                for (int nt = 0; nt < 4; nt++) {
                    asm volatile(
                        "mma.sync.aligned.m16n8k16.row.col.f32.bf16.bf16.f32 "
                        "{%0,%1,%2,%3}, {%4,%5,%6,%7}, {%8,%9}, {%0,%1,%2,%3};\n"
                        : "+f"(acc[mt][nt][0]), "+f"(acc[mt][nt][1]),
                          "+f"(acc[mt][nt][2]), "+f"(acc[mt][nt][3])
                        : "r"(a0), "r"(a1), "r"(a2), "r"(a3),
                          "r"(bfr[nt][0]), "r"(bfr[nt][1]));
                }
            }
        }
        __syncthreads();
    }

#pragma unroll
    for (int mt = 0; mt < 4; mt++) {
        int row0 = m0 + wm + mt * 16 + lr;
#pragma unroll
        for (int nt = 0; nt < 4; nt++) {
            int col = n0 + wn + nt * 8 + lc;
            float v0 = acc[mt][nt][0], v1 = acc[mt][nt][1];
            float v2 = acc[mt][nt][2], v3 = acc[mt][nt][3];
            if (EPI == 1) {
                float b0 = bias[col], b1 = bias[col + 1];
                v0 = softplusf(v0 + b0); v1 = softplusf(v1 + b1);
                v2 = softplusf(v2 + b0); v3 = softplusf(v3 + b1);
            }
            *(float2*)&Cb[(size_t)row0 * ldc + col] = make_float2(v0, v1);
            *(float2*)&Cb[(size_t)(row0 + 8) * ldc + col] = make_float2(v2, v3);
        }
    }
}

// ---------------- 3) depthwise causal conv (width 4) + SiLU -> fp32 + split ----------------
__global__ void conv_silu_kernel(const float* __restrict__ xz,
                                 const float* __restrict__ cw,
                                 const float* __restrict__ cb,
                                 float* __restrict__ xc,
                                 bf16* __restrict__ xch, bf16* __restrict__ xcl) {
    int d = blockIdx.x * 256 + threadIdx.x;
    int b = blockIdx.z;
    int l0 = blockIdx.y * 64;
    float c0 = cw[d * 4 + 0], c1 = cw[d * 4 + 1], c2 = cw[d * 4 + 2], c3 = cw[d * 4 + 3];
    float bias = cb[d];
    float w0 = 0.f, w1 = 0.f, w2 = 0.f;
#pragma unroll
    for (int j = 3; j >= 1; j--) {
        int l = l0 - j;
        float v = (l >= 0) ? xz[((size_t)(b * L_ + l)) * (2 * DI) + d] : 0.f;
        if (j == 3) w0 = v;
        else if (j == 2) w1 = v;
        else w2 = v;
    }
    for (int i = 0; i < 64; i++) {
        int l = l0 + i;
        float xv = xz[((size_t)(b * L_ + l)) * (2 * DI) + d];
        float a = bias + c0 * w0 + c1 * w1 + c2 * w2 + c3 * xv;
        float sv = siluf(a);
        size_t o = ((size_t)(b * L_ + l)) * DI + d;
        xc[o] = sv;
        bf16 hh, ll; split2(sv, hh, ll);
        xch[o] = hh; xcl[o] = ll;
        w0 = w1; w1 = w2; w2 = xv;
    }
}

// ---------------- 4) split-K reduce for x_dbl -> fp32 + split ----------------
__global__ void xdbl_reduce_kernel(const float* __restrict__ part, float* __restrict__ out,
                                   bf16* __restrict__ oh, bf16* __restrict__ ol) {
    int idx = blockIdx.x * 256 + threadIdx.x;
    if (idx >= T_ * NX) return;
    int t = idx / NX;
    int n = idx - t * NX;
    float s = 0.f;
#pragma unroll
    for (int z = 0; z < KSPLITS; z++)
        s += part[((size_t)z * T_ + t) * NXPAD + n];
    out[idx] = s;
    bf16 hh, ll; split2(s, hh, ll);
    oh[idx] = hh; ol[idx] = ll;
}

// ---------------- 5) selective scan ----------------
__global__ void scan_kernel(const float* __restrict__ dt, const float* __restrict__ xc,
                            const float* __restrict__ xdbl, const float* __restrict__ A_log,
                            float* __restrict__ ys) {
    int tid = threadIdx.x;
    int lane = tid & 15;
    int grp = tid >> 4;
    int ch = blockIdx.x * 8 + grp;
    int b = ch >> 12;
    int d = ch & (DI - 1);
    float Aval = -expf(A_log[d * DS + lane]);
    float h = 0.f;
    size_t baseRow = (size_t)b * L_;
    for (int l = 0; l < L_; l++) {
        size_t t = baseRow + l;
        float dtv = dt[t * DI + d];
        float xv = xc[t * DI + d];
        const float* xd = xdbl + t * NX;
        float bs = xd[DTR + lane];
        float cs = xd[DTR + DS + lane];
        float dA = __expf(dtv * Aval);
        h = fmaf(dA, h, dtv * xv * bs);
        float yp = h * cs;
        yp += __shfl_xor_sync(0xffffffffu, yp, 8);
        yp += __shfl_xor_sync(0xffffffffu, yp, 4);
        yp += __shfl_xor_sync(0xffffffffu, yp, 2);
        yp += __shfl_xor_sync(0xffffffffu, yp, 1);
        if (lane == 0) ys[t * DI + d] = yp;
    }
}

// ---------------- 6) gating -> split bf16 y ----------------
__global__ void gate_kernel(const float* __restrict__ xz, const float* __restrict__ xc,
                            const float* __restrict__ Dp, const float* __restrict__ ys,
                            bf16* __restrict__ yh, bf16* __restrict__ yl) {
    size_t idx = (size_t)blockIdx.x * 256 + threadIdx.x;
    size_t t = idx / DI;
    int d = (int)(idx - t * DI);
    float z = xz[t * (2 * DI) + DI + d];
    float y = (ys[idx] + xc[idx] * Dp[d]) * siluf(z);
    bf16 hh, ll; split2(y, hh, ll);
    yh[idx] = hh; yl[idx] = ll;
}

// ---------------- launch ----------------
extern "C" void kernel_launch(void* const* d_in, const int* in_sizes, int n_in,
                              void* d_out, int out_size) {
    const float* hidden   = (const float*)d_in[0];
    const float* residual = (const float*)d_in[1];
    const float* norm_w   = (const float*)d_in[2];
    const float* in_proj  = (const float*)d_in[3];
    const float* conv_w   = (const float*)d_in[4];
    const float* conv_b   = (const float*)d_in[5];
    const float* x_proj   = (const float*)d_in[6];
    const float* dt_proj  = (const float*)d_in[7];
    const float* dt_bias  = (const float*)d_in[8];
    const float* A_log    = (const float*)d_in[9];
    const float* D_param  = (const float*)d_in[10];
    const float* out_proj = (const float*)d_in[11];

    float* out = (float*)d_out;
    float* resid_out = (out_size >= 2 * T_ * DM) ? out + (size_t)T_ * DM : nullptr;

    // weight splits (recomputed each launch; deterministic)
    wsplit4<<<(2 * DI * DM / 4 + 255) / 256, 256>>>(in_proj, g_wip_h, g_wip_l, 2 * DI * DM / 4);
    wsplit4<<<(DM * DI / 4 + 255) / 256, 256>>>(out_proj, g_wop_h, g_wop_l, DM * DI / 4);
    wsplit4<<<(DI * DTR / 4 + 255) / 256, 256>>>(dt_proj, g_wdt_h, g_wdt_l, DI * DTR / 4);
    wsplit_pad<<<NXPAD * DI / 256, 256>>>(x_proj, g_wxp_h, g_wxp_l);

    // 1) add + rmsnorm -> split hs
    addnorm_kernel<<<T_, 256>>>(hidden, residual, norm_w, resid_out, g_hsh, g_hsl);

    // 2) xz = hs @ in_proj^T : M=2048, N=8192, K=2048
    bgemm<0><<<dim3(2 * DI / 128, T_ / 128, 1), 256>>>(
        g_hsh, g_hsl, g_wip_h, g_wip_l, g_xz, T_, 2 * DI, DM, DM, 2 * DI, DM, nullptr);

    // 3) depthwise conv + silu -> xc fp32 + split
    conv_silu_kernel<<<dim3(DI / 256, L_ / 64, B_), 256>>>(g_xz, conv_w, conv_b, g_xc, g_xch, g_xcl);

    // 4) x_dbl partials: M=2048, N=256(padded), K=4096, split-K=8
    bgemm<0><<<dim3(NXPAD / 128, T_ / 128, KSPLITS), 256>>>(
        g_xch, g_xcl, g_wxp_h, g_wxp_l, g_xdblp, T_, NXPAD, DI, DI, NXPAD, DI / KSPLITS, nullptr);
    xdbl_reduce_kernel<<<(T_ * NX + 255) / 256, 256>>>(g_xdblp, g_xdbl, g_xdh, g_xdl);

    // 5) dt = softplus(x_dbl[:, :128] @ dt_proj^T + b) : M=2048, N=4096, K=128
    bgemm<1><<<dim3(DI / 128, T_ / 128, 1), 256>>>(
        g_xdh, g_xdl, g_wdt_h, g_wdt_l, g_dt, T_, DI, NX, DTR, DI, DTR, dt_bias);

    // 6) selective scan
    scan_kernel<<<B_ * DI / 8, 128>>>(g_dt, g_xc, g_xdbl, A_log, g_ys);

    // 7) gate -> split y
    gate_kernel<<<(int)(((size_t)T_ * DI) / 256), 256>>>(g_xz, g_xc, D_param, g_ys, g_yh, g_yl);

    // 8) out = y @ out_proj^T : M=2048, N=2048, K=4096
    bgemm<0><<<dim3(DM / 128, T_ / 128, 1), 256>>>(
        g_yh, g_yl, g_wop_h, g_wop_l, out, T_, DM, DI, DI, DM, DI, nullptr);
}

// round 5
// speedup vs baseline: 1.0044x; 1.0044x over previous
#include <cuda_runtime.h>
#include <cuda_bf16.h>
#include <math.h>
#include <stdint.h>

typedef __nv_bfloat16 bf16;

#define B_   2
#define L_   1024
#define DM   2048
#define DI   4096
#define DS   16
#define DTR  128
#define T_   (B_*L_)        // 2048 tokens
#define NX   160            // dt_rank + 2*d_state
#define NXPAD 256
#define KSPLITS 8
#define ASTR 40             // smem row stride (bf16 elems), conflict-free for frag loads

// ---------------- scratch (static __device__ arrays; no allocation) ----------------
__device__ float g_xz   [(size_t)T_*2*DI];          // in_proj output (fp32)
__device__ float g_xc   [(size_t)T_*DI];            // conv+silu(x) fp32 (scan input)
__device__ float g_xdblp[(size_t)KSPLITS*T_*NXPAD]; // split-K partials
__device__ float g_xdbl [(size_t)T_*NX];
__device__ float g_dt   [(size_t)T_*DI];
__device__ float g_ys   [(size_t)T_*DI];

// split-bf16 activation / weight buffers
__device__ bf16 g_hsh[(size_t)T_*DM],   g_hsl[(size_t)T_*DM];
__device__ bf16 g_xch[(size_t)T_*DI],   g_xcl[(size_t)T_*DI];
__device__ bf16 g_xdh[(size_t)T_*NX],   g_xdl[(size_t)T_*NX];
__device__ bf16 g_yh [(size_t)T_*DI],   g_yl [(size_t)T_*DI];
__device__ bf16 g_wip_h[(size_t)2*DI*DM], g_wip_l[(size_t)2*DI*DM];
__device__ bf16 g_wxp_h[(size_t)NXPAD*DI], g_wxp_l[(size_t)NXPAD*DI];
__device__ bf16 g_wdt_h[(size_t)DI*DTR],  g_wdt_l[(size_t)DI*DTR];
__device__ bf16 g_wop_h[(size_t)DM*DI],   g_wop_l[(size_t)DM*DI];

// ---------------- helpers ----------------
__device__ __forceinline__ float siluf(float x) { return x / (1.0f + expf(-x)); }
__device__ __forceinline__ float softplusf(float x) { return (x > 20.0f) ? x : log1pf(expf(x)); }
__device__ __forceinline__ void split2(float x, bf16& h, bf16& l) {
    h = __float2bfloat16(x);
    l = __float2bfloat16(x - __bfloat162float(h));
}

// ---------------- weight splitters (vectorized) ----------------
__global__ void wsplit4(const float4* __restrict__ w, __nv_bfloat162* __restrict__ hi,
                        __nv_bfloat162* __restrict__ lo, int n4) {
    int i = blockIdx.x * 256 + threadIdx.x;
    if (i >= n4) return;
    float4 v = w[i];
    bf16 h0, h1, h2, h3, l0, l1, l2, l3;
    split2(v.x, h0, l0); split2(v.y, h1, l1);
    split2(v.z, h2, l2); split2(v.w, h3, l3);
    hi[2 * i + 0] = __nv_bfloat162(h0, h1);
    hi[2 * i + 1] = __nv_bfloat162(h2, h3);
    lo[2 * i + 0] = __nv_bfloat162(l0, l1);
    lo[2 * i + 1] = __nv_bfloat162(l2, l3);
}

// x_proj weights padded from [160][4096] to [256][4096] (zero rows 160..255), float4 path
__global__ void wsplit_pad(const float4* __restrict__ w, __nv_bfloat162* __restrict__ hi,
                           __nv_bfloat162* __restrict__ lo) {
    int i = blockIdx.x * 256 + threadIdx.x;   // over NXPAD*DI/4
    int n = i >> 10;                          // / (DI/4)
    float4 v = make_float4(0.f, 0.f, 0.f, 0.f);
    if (n < NX) v = w[(size_t)n * (DI / 4) + (i & (DI / 4 - 1))];
    bf16 h0, h1, h2, h3, l0, l1, l2, l3;
    split2(v.x, h0, l0); split2(v.y, h1, l1);
    split2(v.z, h2, l2); split2(v.w, h3, l3);
    hi[2 * i + 0] = __nv_bfloat162(h0, h1);
    hi[2 * i + 1] = __nv_bfloat162(h2, h3);
    lo[2 * i + 0] = __nv_bfloat162(l0, l1);
    lo[2 * i + 1] = __nv_bfloat162(l2, l3);
}

// ---------------- 1) fused add + RMSNorm -> split bf16 hs ----------------
__global__ void addnorm_kernel(const float* __restrict__ h, const float* __restrict__ r,
                               const float* __restrict__ w, float* __restrict__ resid_out,
                               bf16* __restrict__ hsh, bf16* __restrict__ hsl) {
    int t = blockIdx.x;
    int tid = threadIdx.x;
    const float* hp = h + (size_t)t * DM;
    const float* rp = r + (size_t)t * DM;
    float v[8];
    float ss = 0.f;
#pragma unroll
    for (int i = 0; i < 8; i++) {
        int c = tid + i * 256;
        float x = hp[c] + rp[c];
        v[i] = x;
        ss += x * x;
    }
    __shared__ float red[256];
    red[tid] = ss;
    __syncthreads();
    for (int s = 128; s > 0; s >>= 1) {
        if (tid < s) red[tid] += red[tid + s];
        __syncthreads();
    }
    float scale = rsqrtf(red[0] / (float)DM + 1e-5f);
#pragma unroll
    for (int i = 0; i < 8; i++) {
        int c = tid + i * 256;
        if (resid_out) resid_out[(size_t)t * DM + c] = v[i];
        float y = v[i] * scale * w[c];
        bf16 hh, ll; split2(y, hh, ll);
        hsh[(size_t)t * DM + c] = hh;
        hsl[(size_t)t * DM + c] = ll;
    }
}

// ---------------- 2) split-bf16 tensor-core GEMM ----------------
// C[M,N] = A[M,K] * W[N,K]^T with A = Ahi+Alo, W = Whi+Wlo (drop lo*lo).
// 128x128 CTA tile, 8 warps (2x4), warp tile 64x32, BK=32, cp.async double buffer.
// NOTE: no min-blocks clause — accumulators must stay in registers (round-3 spill bug).
template<int EPI>
__global__ void __launch_bounds__(256)
bgemm(const bf16* __restrict__ Ahi, const bf16* __restrict__ Alo,
      const bf16* __restrict__ Whi, const bf16* __restrict__ Wlo,
      float* __restrict__ C, int M, int N, int lda, int ldw, int ldc,
      int klen, const float* __restrict__ bias) {
    __shared__ __align__(16) bf16 As[2][128][ASTR];
    __shared__ __align__(16) bf16 Wsm[2][128][ASTR];
    int tid = threadIdx.x;
    int m0 = blockIdx.y * 128, n0 = blockIdx.x * 128;
    int kstart = blockIdx.z * klen;
    int KS = klen / 32;
    int S = 3 * KS;
    float* Cb = C + (size_t)blockIdx.z * M * ldc;

    int r = tid >> 1;
    int cc = (tid & 1) * 16;
    uint32_t sa_base[2], sw_base[2];
#pragma unroll
    for (int b = 0; b < 2; b++) {
        sa_base[b] = (uint32_t)__cvta_generic_to_shared(&As[b][r][cc]);
        sw_base[b] = (uint32_t)__cvta_generic_to_shared(&Wsm[b][r][cc]);
    }

    int warp = tid >> 5, lane = tid & 31;
    int wm = (warp >> 2) * 64;
    int wn = (warp & 3) * 32;
    int lr = lane >> 2;
    int lc = (lane & 3) * 2;

    float acc[4][4][4];
#pragma unroll
    for (int mt = 0; mt < 4; mt++)
#pragma unroll
        for (int nt = 0; nt < 4; nt++)
#pragma unroll
            for (int q = 0; q < 4; q++) acc[mt][nt][q] = 0.f;

    auto issue = [&](int s, int buf) {
        int p = s / KS;
        int kk = kstart + (s - p * KS) * 32;
        const bf16* Ag = (p == 1 ? Alo : Ahi) + (size_t)(m0 + r) * lda + kk + cc;
        const bf16* Wg = (p == 2 ? Wlo : Whi) + (size_t)(n0 + r) * ldw + kk + cc;
        asm volatile("cp.async.cg.shared.global [%0], [%1], 16;\n" ::"r"(sa_base[buf]), "l"(Ag));
        asm volatile("cp.async.cg.shared.global [%0], [%1], 16;\n" ::"r"(sa_base[buf] + 16), "l"(Ag + 8));
        asm volatile("cp.async.cg.shared.global [%0], [%1], 16;\n" ::"r"(sw_base[buf]), "l"(Wg));
        asm volatile("cp.async.cg.shared.global [%0], [%1], 16;\n" ::"r"(sw_base[buf] + 16), "l"(Wg + 8));
        asm volatile("cp.async.commit_group;\n");
    };

    issue(0, 0);
    for (int s = 0; s < S; s++) {
        int buf = s & 1;
        if (s + 1 < S) {
            issue(s + 1, buf ^ 1);
            asm volatile("cp.async.wait_group 1;\n");
        } else {
            asm volatile("cp.async.wait_group 0;\n");
        }
        __syncthreads();
#pragma unroll
        for (int ko = 0; ko < 32; ko += 16) {
            uint32_t bfr[4][2];
#pragma unroll
            for (int nt = 0; nt < 4; nt++) {
                const bf16* wp = &Wsm[buf][wn + nt * 8 + lr][ko + lc];
                bfr[nt][0] = *(const uint32_t*)wp;
                bfr[nt][1] = *(const uint32_t*)(wp + 8);
            }
#pragma unroll
            for (int mt = 0; mt < 4; mt++) {
                const bf16* ap = &As[buf][wm + mt * 16 + lr][ko + lc];
                uint32_t a0 = *(const uint32_t*)ap;
                uint32_t a1 = *(const uint32_t*)(ap + 8 * ASTR);
                uint32_t a2 = *(const uint32_t*)(ap + 8);
                uint32_t a3 = *(const uint32_t*)(ap + 8 * ASTR + 8);
#pragma unroll
                for (int nt = 0; nt < 4; nt++) {
                    asm volatile(
                        "mma.sync.aligned.m16n8k16.row.col.f32.bf16.bf16.f32 "
                        "{%0,%1,%2,%3}, {%4,%5,%6,%7}, {%8,%9}, {%0,%1,%2,%3};\n"
                        : "+f"(acc[mt][nt][0]), "+f"(acc[mt][nt][1]),
                          "+f"(acc[mt][nt][2]), "+f"(acc[mt][nt][3])
                        : "r"(a0), "r"(a1), "r"(a2), "r"(a3),
                          "r"(bfr[nt][0]), "r"(bfr[nt][1]));
                }
            }
        }
        __syncthreads();
    }

#pragma unroll
    for (int mt = 0; mt < 4; mt++) {
        int row0 = m0 + wm + mt * 16 + lr;
#pragma unroll
        for (int nt = 0; nt < 4; nt++) {
            int col = n0 + wn + nt * 8 + lc;
            float v0 = acc[mt][nt][0], v1 = acc[mt][nt][1];
            float v2 = acc[mt][nt][2], v3 = acc[mt][nt][3];
            if (EPI == 1) {
                float b0 = bias[col], b1 = bias[col + 1];
                v0 = softplusf(v0 + b0); v1 = softplusf(v1 + b1);
                v2 = softplusf(v2 + b0); v3 = softplusf(v3 + b1);
            }
            *(float2*)&Cb[(size_t)row0 * ldc + col] = make_float2(v0, v1);
            *(float2*)&Cb[(size_t)(row0 + 8) * ldc + col] = make_float2(v2, v3);
        }
    }
}

// ---------------- 3) depthwise causal conv (width 4) + SiLU -> fp32 + split ----------------
__global__ void conv_silu_kernel(const float* __restrict__ xz,
                                 const float* __restrict__ cw,
                                 const float* __restrict__ cb,
                                 float* __restrict__ xc,
                                 bf16* __restrict__ xch, bf16* __restrict__ xcl) {
    int d = blockIdx.x * 256 + threadIdx.x;
    int b = blockIdx.z;
    int l0 = blockIdx.y * 64;
    float c0 = cw[d * 4 + 0], c1 = cw[d * 4 + 1], c2 = cw[d * 4 + 2], c3 = cw[d * 4 + 3];
    float bias = cb[d];
    float w0 = 0.f, w1 = 0.f, w2 = 0.f;
#pragma unroll
    for (int j = 3; j >= 1; j--) {
        int l = l0 - j;
        float v = (l >= 0) ? xz[((size_t)(b * L_ + l)) * (2 * DI) + d] : 0.f;
        if (j == 3) w0 = v;
        else if (j == 2) w1 = v;
        else w2 = v;
    }
    for (int i = 0; i < 64; i++) {
        int l = l0 + i;
        float xv = xz[((size_t)(b * L_ + l)) * (2 * DI) + d];
        float a = bias + c0 * w0 + c1 * w1 + c2 * w2 + c3 * xv;
        float sv = siluf(a);
        size_t o = ((size_t)(b * L_ + l)) * DI + d;
        xc[o] = sv;
        bf16 hh, ll; split2(sv, hh, ll);
        xch[o] = hh; xcl[o] = ll;
        w0 = w1; w1 = w2; w2 = xv;
    }
}

// ---------------- 4) split-K reduce for x_dbl -> fp32 + split ----------------
__global__ void xdbl_reduce_kernel(const float* __restrict__ part, float* __restrict__ out,
                                   bf16* __restrict__ oh, bf16* __restrict__ ol) {
    int idx = blockIdx.x * 256 + threadIdx.x;
    if (idx >= T_ * NX) return;
    int t = idx / NX;
    int n = idx - t * NX;
    float s = 0.f;
#pragma unroll
    for (int z = 0; z < KSPLITS; z++)
        s += part[((size_t)z * T_ + t) * NXPAD + n];
    out[idx] = s;
    bf16 hh, ll; split2(s, hh, ll);
    oh[idx] = hh; ol[idx] = ll;
}

// ---------------- 5) selective scan ----------------
__global__ void scan_kernel(const float* __restrict__ dt, const float* __restrict__ xc,
                            const float* __restrict__ xdbl, const float* __restrict__ A_log,
                            float* __restrict__ ys) {
    int tid = threadIdx.x;
    int lane = tid & 15;
    int grp = tid >> 4;
    int ch = blockIdx.x * 8 + grp;
    int b = ch >> 12;
    int d = ch & (DI - 1);
    float Aval = -expf(A_log[d * DS + lane]);
    float h = 0.f;
    size_t baseRow = (size_t)b * L_;
    for (int l = 0; l < L_; l++) {
        size_t t = baseRow + l;
        float dtv = dt[t * DI + d];
        float xv = xc[t * DI + d];
        const float* xd = xdbl + t * NX;
        float bs = xd[DTR + lane];
        float cs = xd[DTR + DS + lane];
        float dA = __expf(dtv * Aval);
        h = fmaf(dA, h, dtv * xv * bs);
        float yp = h * cs;
        yp += __shfl_xor_sync(0xffffffffu, yp, 8);
        yp += __shfl_xor_sync(0xffffffffu, yp, 4);
        yp += __shfl_xor_sync(0xffffffffu, yp, 2);
        yp += __shfl_xor_sync(0xffffffffu, yp, 1);
        if (lane == 0) ys[t * DI + d] = yp;
    }
}

// ---------------- 6) gating -> split bf16 y ----------------
__global__ void gate_kernel(const float* __restrict__ xz, const float* __restrict__ xc,
                            const float* __restrict__ Dp, const float* __restrict__ ys,
                            bf16* __restrict__ yh, bf16* __restrict__ yl) {
    size_t idx = (size_t)blockIdx.x * 256 + threadIdx.x;
    size_t t = idx / DI;
    int d = (int)(idx - t * DI);
    float z = xz[t * (2 * DI) + DI + d];
    float y = (ys[idx] + xc[idx] * Dp[d]) * siluf(z);
    bf16 hh, ll; split2(y, hh, ll);
    yh[idx] = hh; yl[idx] = ll;
}

// ---------------- launch ----------------
extern "C" void kernel_launch(void* const* d_in, const int* in_sizes, int n_in,
                              void* d_out, int out_size) {
    const float* hidden   = (const float*)d_in[0];
    const float* residual = (const float*)d_in[1];
    const float* norm_w   = (const float*)d_in[2];
    const float* in_proj  = (const float*)d_in[3];
    const float* conv_w   = (const float*)d_in[4];
    const float* conv_b   = (const float*)d_in[5];
    const float* x_proj   = (const float*)d_in[6];
    const float* dt_proj  = (const float*)d_in[7];
    const float* dt_bias  = (const float*)d_in[8];
    const float* A_log    = (const float*)d_in[9];
    const float* D_param  = (const float*)d_in[10];
    const float* out_proj = (const float*)d_in[11];

    float* out = (float*)d_out;
    float* resid_out = (out_size >= 2 * T_ * DM) ? out + (size_t)T_ * DM : nullptr;

    // weight splits (recomputed each launch; deterministic)
    wsplit4<<<(2 * DI * DM / 4 + 255) / 256, 256>>>(
        (const float4*)in_proj, (__nv_bfloat162*)g_wip_h, (__nv_bfloat162*)g_wip_l, 2 * DI * DM / 4);
    wsplit4<<<(DM * DI / 4 + 255) / 256, 256>>>(
        (const float4*)out_proj, (__nv_bfloat162*)g_wop_h, (__nv_bfloat162*)g_wop_l, DM * DI / 4);
    wsplit4<<<(DI * DTR / 4 + 255) / 256, 256>>>(
        (const float4*)dt_proj, (__nv_bfloat162*)g_wdt_h, (__nv_bfloat162*)g_wdt_l, DI * DTR / 4);
    wsplit_pad<<<NXPAD * DI / 4 / 256, 256>>>(
        (const float4*)x_proj, (__nv_bfloat162*)g_wxp_h, (__nv_bfloat162*)g_wxp_l);

    // 1) add + rmsnorm -> split hs
    addnorm_kernel<<<T_, 256>>>(hidden, residual, norm_w, resid_out, g_hsh, g_hsl);

    // 2) xz = hs @ in_proj^T : M=2048, N=8192, K=2048
    bgemm<0><<<dim3(2 * DI / 128, T_ / 128, 1), 256>>>(
        g_hsh, g_hsl, g_wip_h, g_wip_l, g_xz, T_, 2 * DI, DM, DM, 2 * DI, DM, nullptr);

    // 3) depthwise conv + silu -> xc fp32 + split
    conv_silu_kernel<<<dim3(DI / 256, L_ / 64, B_), 256>>>(g_xz, conv_w, conv_b, g_xc, g_xch, g_xcl);

    // 4) x_dbl partials: M=2048, N=256(padded), K=4096, split-K=8
    bgemm<0><<<dim3(NXPAD / 128, T_ / 128, KSPLITS), 256>>>(
        g_xch, g_xcl, g_wxp_h, g_wxp_l, g_xdblp, T_, NXPAD, DI, DI, NXPAD, DI / KSPLITS, nullptr);
    xdbl_reduce_kernel<<<(T_ * NX + 255) / 256, 256>>>(g_xdblp, g_xdbl, g_xdh, g_xdl);

    // 5) dt = softplus(x_dbl[:, :128] @ dt_proj^T + b) : M=2048, N=4096, K=128
    bgemm<1><<<dim3(DI / 128, T_ / 128, 1), 256>>>(
        g_xdh, g_xdl, g_wdt_h, g_wdt_l, g_dt, T_, DI, NX, DTR, DI, DTR, dt_bias);

    // 6) selective scan
    scan_kernel<<<B_ * DI / 8, 128>>>(g_dt, g_xc, g_xdbl, A_log, g_ys);

    // 7) gate -> split y
    gate_kernel<<<(int)(((size_t)T_ * DI) / 256), 256>>>(g_xz, g_xc, D_param, g_ys, g_yh, g_yl);

    // 8) out = y @ out_proj^T : M=2048, N=2048, K=4096
    bgemm<0><<<dim3(DM / 128, T_ / 128, 1), 256>>>(
        g_yh, g_yl, g_wop_h, g_wop_l, out, T_, DM, DI, DI, DM, DI, nullptr);
}

// round 7
// speedup vs baseline: 6.0651x; 6.0388x over previous
#include <cuda_runtime.h>
#include <cuda_bf16.h>
#include <math.h>
#include <stdint.h>

#define B_   2
#define L_   1024
#define DM   2048
#define DI   4096
#define DS   16
#define DTR  128
#define T_   (B_*L_)        // 2048 tokens
#define NX   160            // dt_rank + 2*d_state
#define NXPAD 256
#define KSPLITS 8

// ---------------- scratch (static __device__ arrays; no allocation) ----------------
__device__ float g_hs   [(size_t)T_*DM];
__device__ float g_xz   [(size_t)T_*2*DI];
__device__ float g_xc   [(size_t)T_*DI];
__device__ float g_xdblp[(size_t)KSPLITS*T_*NXPAD];
__device__ float g_xdbl [(size_t)T_*NX];
__device__ float g_dt   [(size_t)T_*DI];
__device__ float g_ys   [(size_t)T_*DI];

// ---------------- helpers ----------------
__device__ __forceinline__ float siluf(float x) { return x / (1.0f + expf(-x)); }
__device__ __forceinline__ float softplusf(float x) { return (x > 20.0f) ? x : log1pf(expf(x)); }

typedef unsigned long long u64;

__device__ __forceinline__ u64 fma2(u64 a, u64 b, u64 c) {
    u64 d;
    asm("fma.rn.f32x2 %0, %1, %2, %3;" : "=l"(d) : "l"(a), "l"(b), "l"(c));
    return d;
}
__device__ __forceinline__ u64 dup2(float x) {
    u64 d;
    asm("mov.b64 %0, {%1, %1};" : "=l"(d) : "f"(x));
    return d;
}
__device__ __forceinline__ float2 unpk(u64 v) {
    float2 f;
    asm("mov.b64 {%0, %1}, %2;" : "=f"(f.x), "=f"(f.y) : "l"(v));
    return f;
}

// ---------------- 1) fused add + RMSNorm ----------------
__global__ void addnorm_kernel(const float* __restrict__ h, const float* __restrict__ r,
                               const float* __restrict__ w, float* __restrict__ resid_out,
                               float* __restrict__ hs) {
    int t = blockIdx.x;
    int tid = threadIdx.x;
    const float* hp = h + (size_t)t * DM;
    const float* rp = r + (size_t)t * DM;
    float v[8];
    float ss = 0.f;
#pragma unroll
    for (int i = 0; i < 8; i++) {
        int c = tid + i * 256;
        float x = hp[c] + rp[c];
        v[i] = x;
        ss += x * x;
    }
    __shared__ float red[256];
    red[tid] = ss;
    __syncthreads();
    for (int s = 128; s > 0; s >>= 1) {
        if (tid < s) red[tid] += red[tid + s];
        __syncthreads();
    }
    float scale = rsqrtf(red[0] / (float)DM + 1e-5f);
#pragma unroll
    for (int i = 0; i < 8; i++) {
        int c = tid + i * 256;
        if (resid_out) resid_out[(size_t)t * DM + c] = v[i];
        hs[(size_t)t * DM + c] = v[i] * scale * w[c];
    }
}

// ---------------- 2) fp32 SGEMM with packed f32x2 FMA ----------------
// C[M,N] = A[M,K] * W[N,K]^T. 128x128 CTA tile, BK=16, 256 threads.
// Register-staged double buffering (one __syncthreads per stage).
// Per thread: rows {ty*4+i, 64+ty*4+i}, cols {tx*4..+3, 64+tx*4..+3};
// accumulate in 32 packed f32x2 regs. blockIdx.z = split-K slab.
template<int EPI, bool NGUARD>
__global__ void __launch_bounds__(256)
sgemm2(const float* __restrict__ A, const float* __restrict__ W, float* __restrict__ C,
       int M, int Nlog, int lda, int ldw, int ldc, int klen,
       const float* __restrict__ bias) {
    __shared__ float As[2][16][132];
    __shared__ float Ws[2][16][132];
    int tid = threadIdx.x;
    int m0 = blockIdx.y * 128, n0 = blockIdx.x * 128;
    int kstart = blockIdx.z * klen;
    float* Cb = C + (size_t)blockIdx.z * M * ldc;

    int r = tid >> 1;            // 0..127
    int k8 = (tid & 1) * 8;      // 0 or 8
    const float* Ag = A + (size_t)(m0 + r) * lda + kstart + k8;
    const float* Wg = W + (size_t)(n0 + r) * ldw + kstart + k8;
    bool wvalid = true;
    if (NGUARD) wvalid = (n0 + r) < Nlog;

    int tx = tid & 15, ty = tid >> 4;

    u64 acc[2][4][4];
#pragma unroll
    for (int rh = 0; rh < 2; rh++)
#pragma unroll
        for (int i = 0; i < 4; i++)
#pragma unroll
            for (int j = 0; j < 4; j++) acc[rh][i][j] = 0ull;

    float4 pa0 = *(const float4*)Ag;
    float4 pa1 = *(const float4*)(Ag + 4);
    float4 z4 = make_float4(0.f, 0.f, 0.f, 0.f);
    float4 pw0 = wvalid ? *(const float4*)Wg : z4;
    float4 pw1 = wvalid ? *(const float4*)(Wg + 4) : z4;

    int nst = klen >> 4;
    for (int s = 0; s < nst; s++) {
        int buf = s & 1;
        // stage registers -> smem (transposed to k-major)
        As[buf][k8 + 0][r] = pa0.x; As[buf][k8 + 1][r] = pa0.y;
        As[buf][k8 + 2][r] = pa0.z; As[buf][k8 + 3][r] = pa0.w;
        As[buf][k8 + 4][r] = pa1.x; As[buf][k8 + 5][r] = pa1.y;
        As[buf][k8 + 6][r] = pa1.z; As[buf][k8 + 7][r] = pa1.w;
        Ws[buf][k8 + 0][r] = pw0.x; Ws[buf][k8 + 1][r] = pw0.y;
        Ws[buf][k8 + 2][r] = pw0.z; Ws[buf][k8 + 3][r] = pw0.w;
        Ws[buf][k8 + 4][r] = pw1.x; Ws[buf][k8 + 5][r] = pw1.y;
        Ws[buf][k8 + 6][r] = pw1.z; Ws[buf][k8 + 7][r] = pw1.w;
        __syncthreads();
        // prefetch next stage
        if (s + 1 < nst) {
            Ag += 16; Wg += 16;
            pa0 = *(const float4*)Ag;
            pa1 = *(const float4*)(Ag + 4);
            pw0 = wvalid ? *(const float4*)Wg : z4;
            pw1 = wvalid ? *(const float4*)(Wg + 4) : z4;
        }
        // compute 16 k-steps
#pragma unroll
        for (int kk = 0; kk < 16; kk++) {
            float4 a0 = *(const float4*)&As[buf][kk][ty * 4];
            float4 a1 = *(const float4*)&As[buf][kk][64 + ty * 4];
            ulonglong2 b0 = *(const ulonglong2*)&Ws[buf][kk][tx * 4];
            ulonglong2 b1 = *(const ulonglong2*)&Ws[buf][kk][64 + tx * 4];
            u64 bb[4] = {b0.x, b0.y, b1.x, b1.y};
            float av[2][4] = {{a0.x, a0.y, a0.z, a0.w}, {a1.x, a1.y, a1.z, a1.w}};
#pragma unroll
            for (int rh = 0; rh < 2; rh++)
#pragma unroll
                for (int i = 0; i < 4; i++) {
                    u64 a2 = dup2(av[rh][i]);
#pragma unroll
                    for (int j = 0; j < 4; j++)
                        acc[rh][i][j] = fma2(a2, bb[j], acc[rh][i][j]);
                }
        }
        __syncthreads();
    }

#pragma unroll
    for (int rh = 0; rh < 2; rh++)
#pragma unroll
        for (int i = 0; i < 4; i++) {
            int row = m0 + rh * 64 + ty * 4 + i;
#pragma unroll
            for (int ch = 0; ch < 2; ch++) {
                int col = n0 + ch * 64 + tx * 4;
                float2 lo = unpk(acc[rh][i][ch * 2 + 0]);
                float2 hi = unpk(acc[rh][i][ch * 2 + 1]);
                float v0 = lo.x, v1 = lo.y, v2 = hi.x, v3 = hi.y;
                if (EPI == 1) {
                    v0 = softplusf(v0 + bias[col + 0]);
                    v1 = softplusf(v1 + bias[col + 1]);
                    v2 = softplusf(v2 + bias[col + 2]);
                    v3 = softplusf(v3 + bias[col + 3]);
                }
                *(float4*)&Cb[(size_t)row * ldc + col] = make_float4(v0, v1, v2, v3);
            }
        }
}

// ---------------- 3) depthwise causal conv (width 4) + SiLU ----------------
__global__ void conv_silu_kernel(const float* __restrict__ xz,
                                 const float* __restrict__ cw,
                                 const float* __restrict__ cb,
                                 float* __restrict__ xc) {
    int d = blockIdx.x * 256 + threadIdx.x;
    int b = blockIdx.z;
    int l0 = blockIdx.y * 64;
    float c0 = cw[d * 4 + 0], c1 = cw[d * 4 + 1], c2 = cw[d * 4 + 2], c3 = cw[d * 4 + 3];
    float bias = cb[d];
    float w0 = 0.f, w1 = 0.f, w2 = 0.f;
#pragma unroll
    for (int j = 3; j >= 1; j--) {
        int l = l0 - j;
        float v = (l >= 0) ? xz[((size_t)(b * L_ + l)) * (2 * DI) + d] : 0.f;
        if (j == 3) w0 = v;
        else if (j == 2) w1 = v;
        else w2 = v;
    }
    for (int i = 0; i < 64; i++) {
        int l = l0 + i;
        float xv = xz[((size_t)(b * L_ + l)) * (2 * DI) + d];
        float a = bias + c0 * w0 + c1 * w1 + c2 * w2 + c3 * xv;
        xc[((size_t)(b * L_ + l)) * DI + d] = siluf(a);
        w0 = w1; w1 = w2; w2 = xv;
    }
}

// ---------------- 4) split-K reduce for x_dbl ----------------
__global__ void xdbl_reduce_kernel(const float* __restrict__ part, float* __restrict__ out) {
    int idx = blockIdx.x * 256 + threadIdx.x;
    if (idx >= T_ * NX) return;
    int t = idx / NX;
    int n = idx - t * NX;
    float s = 0.f;
#pragma unroll
    for (int z = 0; z < KSPLITS; z++)
        s += part[((size_t)z * T_ + t) * NXPAD + n];
    out[idx] = s;
}

// ---------------- 5) selective scan ----------------
__global__ void scan_kernel(const float* __restrict__ dt, const float* __restrict__ xc,
                            const float* __restrict__ xdbl, const float* __restrict__ A_log,
                            float* __restrict__ ys) {
    int tid = threadIdx.x;
    int lane = tid & 15;
    int grp = tid >> 4;
    int ch = blockIdx.x * 8 + grp;
    int b = ch >> 12;
    int d = ch & (DI - 1);
    float Aval = -expf(A_log[d * DS + lane]);
    float h = 0.f;
    size_t baseRow = (size_t)b * L_;
    for (int l = 0; l < L_; l++) {
        size_t t = baseRow + l;
        float dtv = dt[t * DI + d];
        float xv = xc[t * DI + d];
        const float* xd = xdbl + t * NX;
        float bs = xd[DTR + lane];
        float cs = xd[DTR + DS + lane];
        float dA = __expf(dtv * Aval);
        h = fmaf(dA, h, dtv * xv * bs);
        float yp = h * cs;
        yp += __shfl_xor_sync(0xffffffffu, yp, 8);
        yp += __shfl_xor_sync(0xffffffffu, yp, 4);
        yp += __shfl_xor_sync(0xffffffffu, yp, 2);
        yp += __shfl_xor_sync(0xffffffffu, yp, 1);
        if (lane == 0) ys[t * DI + d] = yp;
    }
}

// ---------------- 6) gating: y = (ys + xc*D) * silu(z) ----------------
__global__ void gate_kernel(const float* __restrict__ xz, const float* __restrict__ xc,
                            const float* __restrict__ Dp, float* __restrict__ ys) {
    size_t idx = (size_t)blockIdx.x * 256 + threadIdx.x;
    size_t t = idx / DI;
    int d = (int)(idx - t * DI);
    float z = xz[t * (2 * DI) + DI + d];
    float y = (ys[idx] + xc[idx] * Dp[d]) * siluf(z);
    ys[idx] = y;
}

// ---------------- launch ----------------
extern "C" void kernel_launch(void* const* d_in, const int* in_sizes, int n_in,
                              void* d_out, int out_size) {
    const float* hidden   = (const float*)d_in[0];
    const float* residual = (const float*)d_in[1];
    const float* norm_w   = (const float*)d_in[2];
    const float* in_proj  = (const float*)d_in[3];   // [8192, 2048]
    const float* conv_w   = (const float*)d_in[4];
    const float* conv_b   = (const float*)d_in[5];
    const float* x_proj   = (const float*)d_in[6];   // [160, 4096]
    const float* dt_proj  = (const float*)d_in[7];   // [4096, 128]
    const float* dt_bias  = (const float*)d_in[8];
    const float* A_log    = (const float*)d_in[9];
    const float* D_param  = (const float*)d_in[10];
    const float* out_proj = (const float*)d_in[11];  // [2048, 4096]

    float* out = (float*)d_out;
    float* resid_out = (out_size >= 2 * T_ * DM) ? out + (size_t)T_ * DM : nullptr;

    // 1) add + rmsnorm
    addnorm_kernel<<<T_, 256>>>(hidden, residual, norm_w, resid_out, g_hs);

    // 2) xz = hs @ in_proj^T : M=2048, N=8192, K=2048
    sgemm2<0, false><<<dim3(2 * DI / 128, T_ / 128, 1), 256>>>(
        g_hs, in_proj, g_xz, T_, 2 * DI, DM, DM, 2 * DI, DM, nullptr);

    // 3) depthwise conv + silu
    conv_silu_kernel<<<dim3(DI / 256, L_ / 64, B_), 256>>>(g_xz, conv_w, conv_b, g_xc);

    // 4) x_dbl partials: M=2048, N=256(padded,160 valid), K=4096, split-K=8
    sgemm2<0, true><<<dim3(NXPAD / 128, T_ / 128, KSPLITS), 256>>>(
        g_xc, x_proj, g_xdblp, T_, NX, DI, DI, NXPAD, DI / KSPLITS, nullptr);
    xdbl_reduce_kernel<<<(T_ * NX + 255) / 256, 256>>>(g_xdblp, g_xdbl);

    // 5) dt = softplus(x_dbl[:, :128] @ dt_proj^T + b) : M=2048, N=4096, K=128
    sgemm2<1, false><<<dim3(DI / 128, T_ / 128, 1), 256>>>(
        g_xdbl, dt_proj, g_dt, T_, DI, NX, DTR, DI, DTR, dt_bias);

    // 6) selective scan
    scan_kernel<<<B_ * DI / 8, 128>>>(g_dt, g_xc, g_xdbl, A_log, g_ys);

    // 7) gate
    gate_kernel<<<(int)(((size_t)T_ * DI) / 256), 256>>>(g_xz, g_xc, D_param, g_ys);

    // 8) out = y @ out_proj^T : M=2048, N=2048, K=4096
    sgemm2<0, false><<<dim3(DM / 128, T_ / 128, 1), 256>>>(
        g_ys, out_proj, out, T_, DM, DI, DI, DM, DI, nullptr);
}

// round 10
// speedup vs baseline: 6.9772x; 1.1504x over previous
#include <cuda_runtime.h>
#include <cuda_bf16.h>
#include <math.h>
#include <stdint.h>

#define B_   2
#define L_   1024
#define DM   2048
#define DI   4096
#define DS   16
#define DTR  128
#define T_   (B_*L_)        // 2048 tokens
#define NX   160            // dt_rank + 2*d_state
#define NXPAD 256
#define KSPLITS 8

// ---------------- scratch (static __device__ arrays; no allocation) ----------------
__device__ float g_hs   [(size_t)T_*DM];
__device__ float g_xz   [(size_t)T_*2*DI];
__device__ float g_xc   [(size_t)T_*DI];
__device__ float g_xdblp[(size_t)KSPLITS*T_*NXPAD];
__device__ float g_xdbl [(size_t)T_*NX];
__device__ float g_dt   [(size_t)T_*DI];
__device__ float g_ys   [(size_t)T_*DI];

// ---------------- helpers ----------------
__device__ __forceinline__ float siluf(float x) { return x / (1.0f + expf(-x)); }
__device__ __forceinline__ float softplusf(float x) { return (x > 20.0f) ? x : log1pf(expf(x)); }

typedef unsigned long long u64;

__device__ __forceinline__ u64 fma2(u64 a, u64 b, u64 c) {
    u64 d;
    asm("fma.rn.f32x2 %0, %1, %2, %3;" : "=l"(d) : "l"(a), "l"(b), "l"(c));
    return d;
}
__device__ __forceinline__ u64 dup2(float x) {
    u64 d;
    asm("mov.b64 %0, {%1, %1};" : "=l"(d) : "f"(x));
    return d;
}
__device__ __forceinline__ float2 unpk(u64 v) {
    float2 f;
    asm("mov.b64 {%0, %1}, %2;" : "=f"(f.x), "=f"(f.y) : "l"(v));
    return f;
}

// ---------------- 1) fused add + RMSNorm ----------------
__global__ void addnorm_kernel(const float* __restrict__ h, const float* __restrict__ r,
                               const float* __restrict__ w, float* __restrict__ resid_out,
                               float* __restrict__ hs) {
    int t = blockIdx.x;
    int tid = threadIdx.x;
    const float* hp = h + (size_t)t * DM;
    const float* rp = r + (size_t)t * DM;
    float v[8];
    float ss = 0.f;
#pragma unroll
    for (int i = 0; i < 8; i++) {
        int c = tid + i * 256;
        float x = hp[c] + rp[c];
        v[i] = x;
        ss += x * x;
    }
    __shared__ float red[256];
    red[tid] = ss;
    __syncthreads();
    for (int s = 128; s > 0; s >>= 1) {
        if (tid < s) red[tid] += red[tid + s];
        __syncthreads();
    }
    float scale = rsqrtf(red[0] / (float)DM + 1e-5f);
#pragma unroll
    for (int i = 0; i < 8; i++) {
        int c = tid + i * 256;
        if (resid_out) resid_out[(size_t)t * DM + c] = v[i];
        hs[(size_t)t * DM + c] = v[i] * scale * w[c];
    }
}

// ---------------- 2) fp32 SGEMM with packed f32x2 FMA ----------------
// C[M,N] = A[M,K] * W[N,K]^T. 128x128 CTA tile, BK=16, 256 threads, 8x8/thread.
// Double-buffered smem with ONE __syncthreads per stage; 2 CTAs/SM (reg cap 128).
template<int EPI, bool NGUARD>
__global__ void __launch_bounds__(256, 2)
sgemm2(const float* __restrict__ A, const float* __restrict__ W, float* __restrict__ C,
       int M, int Nlog, int lda, int ldw, int ldc, int klen,
       const float* __restrict__ bias) {
    __shared__ float As[2][16][132];
    __shared__ float Ws[2][16][132];
    int tid = threadIdx.x;
    int m0 = blockIdx.y * 128, n0 = blockIdx.x * 128;
    int kstart = blockIdx.z * klen;
    float* Cb = C + (size_t)blockIdx.z * M * ldc;

    int r = tid >> 1;            // 0..127
    int k8 = (tid & 1) * 8;      // 0 or 8
    const float* Ag = A + (size_t)(m0 + r) * lda + kstart + k8;
    const float* Wg = W + (size_t)(n0 + r) * ldw + kstart + k8;
    bool wvalid = true;
    if (NGUARD) wvalid = (n0 + r) < Nlog;

    int tx = tid & 15, ty = tid >> 4;

    u64 acc[2][4][4];
#pragma unroll
    for (int rh = 0; rh < 2; rh++)
#pragma unroll
        for (int i = 0; i < 4; i++)
#pragma unroll
            for (int j = 0; j < 4; j++) acc[rh][i][j] = 0ull;

    float4 z4 = make_float4(0.f, 0.f, 0.f, 0.f);
    // prefetch stage 0, store, prefetch stage 1
    float4 pa0 = *(const float4*)Ag;
    float4 pa1 = *(const float4*)(Ag + 4);
    float4 pw0 = wvalid ? *(const float4*)Wg : z4;
    float4 pw1 = wvalid ? *(const float4*)(Wg + 4) : z4;

    int nst = klen >> 4;

    As[0][k8 + 0][r] = pa0.x; As[0][k8 + 1][r] = pa0.y;
    As[0][k8 + 2][r] = pa0.z; As[0][k8 + 3][r] = pa0.w;
    As[0][k8 + 4][r] = pa1.x; As[0][k8 + 5][r] = pa1.y;
    As[0][k8 + 6][r] = pa1.z; As[0][k8 + 7][r] = pa1.w;
    Ws[0][k8 + 0][r] = pw0.x; Ws[0][k8 + 1][r] = pw0.y;
    Ws[0][k8 + 2][r] = pw0.z; Ws[0][k8 + 3][r] = pw0.w;
    Ws[0][k8 + 4][r] = pw1.x; Ws[0][k8 + 5][r] = pw1.y;
    Ws[0][k8 + 6][r] = pw1.z; Ws[0][k8 + 7][r] = pw1.w;
    if (nst > 1) {
        Ag += 16; Wg += 16;
        pa0 = *(const float4*)Ag;
        pa1 = *(const float4*)(Ag + 4);
        pw0 = wvalid ? *(const float4*)Wg : z4;
        pw1 = wvalid ? *(const float4*)(Wg + 4) : z4;
    }

    for (int s = 0; s < nst; s++) {
        int buf = s & 1;
        __syncthreads();
        if (s + 1 < nst) {
            int b2 = buf ^ 1;
            As[b2][k8 + 0][r] = pa0.x; As[b2][k8 + 1][r] = pa0.y;
            As[b2][k8 + 2][r] = pa0.z; As[b2][k8 + 3][r] = pa0.w;
            As[b2][k8 + 4][r] = pa1.x; As[b2][k8 + 5][r] = pa1.y;
            As[b2][k8 + 6][r] = pa1.z; As[b2][k8 + 7][r] = pa1.w;
            Ws[b2][k8 + 0][r] = pw0.x; Ws[b2][k8 + 1][r] = pw0.y;
            Ws[b2][k8 + 2][r] = pw0.z; Ws[b2][k8 + 3][r] = pw0.w;
            Ws[b2][k8 + 4][r] = pw1.x; Ws[b2][k8 + 5][r] = pw1.y;
            Ws[b2][k8 + 6][r] = pw1.z; Ws[b2][k8 + 7][r] = pw1.w;
            if (s + 2 < nst) {
                Ag += 16; Wg += 16;
                pa0 = *(const float4*)Ag;
                pa1 = *(const float4*)(Ag + 4);
                pw0 = wvalid ? *(const float4*)Wg : z4;
                pw1 = wvalid ? *(const float4*)(Wg + 4) : z4;
            }
        }
        // compute 16 k-steps on buf
#pragma unroll
        for (int kk = 0; kk < 16; kk++) {
            float4 a0 = *(const float4*)&As[buf][kk][ty * 4];
            float4 a1 = *(const float4*)&As[buf][kk][64 + ty * 4];
            ulonglong2 b0 = *(const ulonglong2*)&Ws[buf][kk][tx * 4];
            ulonglong2 b1 = *(const ulonglong2*)&Ws[buf][kk][64 + tx * 4];
            u64 d;
            d = dup2(a0.x);
            acc[0][0][0] = fma2(d, b0.x, acc[0][0][0]);
            acc[0][0][1] = fma2(d, b0.y, acc[0][0][1]);
            acc[0][0][2] = fma2(d, b1.x, acc[0][0][2]);
            acc[0][0][3] = fma2(d, b1.y, acc[0][0][3]);
            d = dup2(a0.y);
            acc[0][1][0] = fma2(d, b0.x, acc[0][1][0]);
            acc[0][1][1] = fma2(d, b0.y, acc[0][1][1]);
            acc[0][1][2] = fma2(d, b1.x, acc[0][1][2]);
            acc[0][1][3] = fma2(d, b1.y, acc[0][1][3]);
            d = dup2(a0.z);
            acc[0][2][0] = fma2(d, b0.x, acc[0][2][0]);
            acc[0][2][1] = fma2(d, b0.y, acc[0][2][1]);
            acc[0][2][2] = fma2(d, b1.x, acc[0][2][2]);
            acc[0][2][3] = fma2(d, b1.y, acc[0][2][3]);
            d = dup2(a0.w);
            acc[0][3][0] = fma2(d, b0.x, acc[0][3][0]);
            acc[0][3][1] = fma2(d, b0.y, acc[0][3][1]);
            acc[0][3][2] = fma2(d, b1.x, acc[0][3][2]);
            acc[0][3][3] = fma2(d, b1.y, acc[0][3][3]);
            d = dup2(a1.x);
            acc[1][0][0] = fma2(d, b0.x, acc[1][0][0]);
            acc[1][0][1] = fma2(d, b0.y, acc[1][0][1]);
            acc[1][0][2] = fma2(d, b1.x, acc[1][0][2]);
            acc[1][0][3] = fma2(d, b1.y, acc[1][0][3]);
            d = dup2(a1.y);
            acc[1][1][0] = fma2(d, b0.x, acc[1][1][0]);
            acc[1][1][1] = fma2(d, b0.y, acc[1][1][1]);
            acc[1][1][2] = fma2(d, b1.x, acc[1][1][2]);
            acc[1][1][3] = fma2(d, b1.y, acc[1][1][3]);
            d = dup2(a1.z);
            acc[1][2][0] = fma2(d, b0.x, acc[1][2][0]);
            acc[1][2][1] = fma2(d, b0.y, acc[1][2][1]);
            acc[1][2][2] = fma2(d, b1.x, acc[1][2][2]);
            acc[1][2][3] = fma2(d, b1.y, acc[1][2][3]);
            d = dup2(a1.w);
            acc[1][3][0] = fma2(d, b0.x, acc[1][3][0]);
            acc[1][3][1] = fma2(d, b0.y, acc[1][3][1]);
            acc[1][3][2] = fma2(d, b1.x, acc[1][3][2]);
            acc[1][3][3] = fma2(d, b1.y, acc[1][3][3]);
        }
    }

#pragma unroll
    for (int rh = 0; rh < 2; rh++)
#pragma unroll
        for (int i = 0; i < 4; i++) {
            int row = m0 + rh * 64 + ty * 4 + i;
#pragma unroll
            for (int ch = 0; ch < 2; ch++) {
                int col = n0 + ch * 64 + tx * 4;
                float2 lo = unpk(acc[rh][i][ch * 2 + 0]);
                float2 hi = unpk(acc[rh][i][ch * 2 + 1]);
                float v0 = lo.x, v1 = lo.y, v2 = hi.x, v3 = hi.y;
                if (EPI == 1) {
                    v0 = softplusf(v0 + bias[col + 0]);
                    v1 = softplusf(v1 + bias[col + 1]);
                    v2 = softplusf(v2 + bias[col + 2]);
                    v3 = softplusf(v3 + bias[col + 3]);
                }
                *(float4*)&Cb[(size_t)row * ldc + col] = make_float4(v0, v1, v2, v3);
            }
        }
}

// ---------------- 3) depthwise causal conv (width 4) + SiLU ----------------
__global__ void conv_silu_kernel(const float* __restrict__ xz,
                                 const float* __restrict__ cw,
                                 const float* __restrict__ cb,
                                 float* __restrict__ xc) {
    int d = blockIdx.x * 256 + threadIdx.x;
    int b = blockIdx.z;
    int l0 = blockIdx.y * 64;
    float c0 = cw[d * 4 + 0], c1 = cw[d * 4 + 1], c2 = cw[d * 4 + 2], c3 = cw[d * 4 + 3];
    float bias = cb[d];
    float w0 = 0.f, w1 = 0.f, w2 = 0.f;
#pragma unroll
    for (int j = 3; j >= 1; j--) {
        int l = l0 - j;
        float v = (l >= 0) ? xz[((size_t)(b * L_ + l)) * (2 * DI) + d] : 0.f;
        if (j == 3) w0 = v;
        else if (j == 2) w1 = v;
        else w2 = v;
    }
    for (int i = 0; i < 64; i++) {
        int l = l0 + i;
        float xv = xz[((size_t)(b * L_ + l)) * (2 * DI) + d];
        float a = bias + c0 * w0 + c1 * w1 + c2 * w2 + c3 * xv;
        xc[((size_t)(b * L_ + l)) * DI + d] = siluf(a);
        w0 = w1; w1 = w2; w2 = xv;
    }
}

// ---------------- 4) split-K reduce for x_dbl ----------------
__global__ void xdbl_reduce_kernel(const float* __restrict__ part, float* __restrict__ out) {
    int idx = blockIdx.x * 256 + threadIdx.x;
    if (idx >= T_ * NX) return;
    int t = idx / NX;
    int n = idx - t * NX;
    float s = 0.f;
#pragma unroll
    for (int z = 0; z < KSPLITS; z++)
        s += part[((size_t)z * T_ + t) * NXPAD + n];
    out[idx] = s;
}

// ---------------- 5) selective scan ----------------
__global__ void scan_kernel(const float* __restrict__ dt, const float* __restrict__ xc,
                            const float* __restrict__ xdbl, const float* __restrict__ A_log,
                            float* __restrict__ ys) {
    int tid = threadIdx.x;
    int lane = tid & 15;
    int grp = tid >> 4;
    int ch = blockIdx.x * 8 + grp;
    int b = ch >> 12;
    int d = ch & (DI - 1);
    float Aval = -expf(A_log[d * DS + lane]);
    float h = 0.f;
    size_t baseRow = (size_t)b * L_;
    for (int l = 0; l < L_; l++) {
        size_t t = baseRow + l;
        float dtv = dt[t * DI + d];
        float xv = xc[t * DI + d];
        const float* xd = xdbl + t * NX;
        float bs = xd[DTR + lane];
        float cs = xd[DTR + DS + lane];
        float dA = __expf(dtv * Aval);
        h = fmaf(dA, h, dtv * xv * bs);
        float yp = h * cs;
        yp += __shfl_xor_sync(0xffffffffu, yp, 8);
        yp += __shfl_xor_sync(0xffffffffu, yp, 4);
        yp += __shfl_xor_sync(0xffffffffu, yp, 2);
        yp += __shfl_xor_sync(0xffffffffu, yp, 1);
        if (lane == 0) ys[t * DI + d] = yp;
    }
}

// ---------------- 6) gating: y = (ys + xc*D) * silu(z) ----------------
__global__ void gate_kernel(const float* __restrict__ xz, const float* __restrict__ xc,
                            const float* __restrict__ Dp, float* __restrict__ ys) {
    size_t idx = (size_t)blockIdx.x * 256 + threadIdx.x;
    size_t t = idx / DI;
    int d = (int)(idx - t * DI);
    float z = xz[t * (2 * DI) + DI + d];
    float y = (ys[idx] + xc[idx] * Dp[d]) * siluf(z);
    ys[idx] = y;
}

// ---------------- launch ----------------
extern "C" void kernel_launch(void* const* d_in, const int* in_sizes, int n_in,
                              void* d_out, int out_size) {
    const float* hidden   = (const float*)d_in[0];
    const float* residual = (const float*)d_in[1];
    const float* norm_w   = (const float*)d_in[2];
    const float* in_proj  = (const float*)d_in[3];   // [8192, 2048]
    const float* conv_w   = (const float*)d_in[4];
    const float* conv_b   = (const float*)d_in[5];
    const float* x_proj   = (const float*)d_in[6];   // [160, 4096]
    const float* dt_proj  = (const float*)d_in[7];   // [4096, 128]
    const float* dt_bias  = (const float*)d_in[8];
    const float* A_log    = (const float*)d_in[9];
    const float* D_param  = (const float*)d_in[10];
    const float* out_proj = (const float*)d_in[11];  // [2048, 4096]

    float* out = (float*)d_out;
    float* resid_out = (out_size >= 2 * T_ * DM) ? out + (size_t)T_ * DM : nullptr;

    // 1) add + rmsnorm
    addnorm_kernel<<<T_, 256>>>(hidden, residual, norm_w, resid_out, g_hs);

    // 2) xz = hs @ in_proj^T : M=2048, N=8192, K=2048
    sgemm2<0, false><<<dim3(2 * DI / 128, T_ / 128, 1), 256>>>(
        g_hs, in_proj, g_xz, T_, 2 * DI, DM, DM, 2 * DI, DM, nullptr);

    // 3) depthwise conv + silu
    conv_silu_kernel<<<dim3(DI / 256, L_ / 64, B_), 256>>>(g_xz, conv_w, conv_b, g_xc);

    // 4) x_dbl partials: M=2048, N=256(padded,160 valid), K=4096, split-K=8
    sgemm2<0, true><<<dim3(NXPAD / 128, T_ / 128, KSPLITS), 256>>>(
        g_xc, x_proj, g_xdblp, T_, NX, DI, DI, NXPAD, DI / KSPLITS, nullptr);
    xdbl_reduce_kernel<<<(T_ * NX + 255) / 256, 256>>>(g_xdblp, g_xdbl);

    // 5) dt = softplus(x_dbl[:, :128] @ dt_proj^T + b) : M=2048, N=4096, K=128
    sgemm2<1, false><<<dim3(DI / 128, T_ / 128, 1), 256>>>(
        g_xdbl, dt_proj, g_dt, T_, DI, NX, DTR, DI, DTR, dt_bias);

    // 6) selective scan
    scan_kernel<<<B_ * DI / 8, 128>>>(g_dt, g_xc, g_xdbl, A_log, g_ys);

    // 7) gate
    gate_kernel<<<(int)(((size_t)T_ * DI) / 256), 256>>>(g_xz, g_xc, D_param, g_ys);

    // 8) out = y @ out_proj^T : M=2048, N=2048, K=4096
    sgemm2<0, false><<<dim3(DM / 128, T_ / 128, 1), 256>>>(
        g_ys, out_proj, out, T_, DM, DI, DI, DM, DI, nullptr);
}